// round 1
// baseline (speedup 1.0000x reference)
#include <cuda_runtime.h>
#include <math.h>

// Problem: FSNeuronDecoupled
//   x:     [8, 2097152, 1] fp32  (16,777,216 elements)
//   d,h,theta: [2] fp32
//   T=8, GRAIN = [0,0,0,0,1,1,1,1], TAU=1
//   per step t: th_t = theta[g]^-(t+1), h_t = h[g]^-(t+1), d_t = d[g]^-(t+1)
//   carry: s = (v > th_t); v -= h_t*s;  y = sum_t d_t*s
//
// Strategy: fully fused elementwise kernel. Pre-kernel computes the 24 scalar
// coefficients (th[8], h[8], d[8]) into a __device__ global so the streaming
// kernel pays only 24 broadcast __ldg's per thread (amortized over 32 elems).

#define T_STEPS 8

__device__ float g_coef[3 * T_STEPS];  // [0:8)=th, [8:16)=h, [16:24)=d

__global__ void coef_kernel(const float* __restrict__ d,
                            const float* __restrict__ h,
                            const float* __restrict__ theta) {
    int t = threadIdx.x;
    if (t < T_STEPS) {
        int g = (t >= T_STEPS / 2) ? 1 : 0;  // GRAIN = [0,0,0,0,1,1,1,1]
        float e = -(float)(t + 1);
        g_coef[t]               = powf(theta[g], e);  // th_t
        g_coef[T_STEPS + t]     = powf(h[g],     e);  // h_t
        g_coef[2 * T_STEPS + t] = powf(d[g],     e);  // d_t
    }
}

__global__ __launch_bounds__(256)
void fsneuron_kernel(const float4* __restrict__ x,
                     float4* __restrict__ y,
                     int n4) {
    // Broadcast coefficient loads (L1/L2 hit; same address for all threads).
    float th[T_STEPS], hh[T_STEPS], dd[T_STEPS];
#pragma unroll
    for (int t = 0; t < T_STEPS; t++) {
        th[t] = __ldg(&g_coef[t]);
        hh[t] = __ldg(&g_coef[T_STEPS + t]);
        dd[t] = __ldg(&g_coef[2 * T_STEPS + t]);
    }

    int idx    = blockIdx.x * blockDim.x + threadIdx.x;
    int stride = gridDim.x * blockDim.x;

    for (int i = idx; i < n4; i += stride) {
        float4 v   = x[i];
        float4 acc = make_float4(0.f, 0.f, 0.f, 0.f);
#pragma unroll
        for (int t = 0; t < T_STEPS; t++) {
            const float tht = th[t], ht = hh[t], dt = dd[t];
            if (v.x > tht) { v.x -= ht; acc.x += dt; }
            if (v.y > tht) { v.y -= ht; acc.y += dt; }
            if (v.z > tht) { v.z -= ht; acc.z += dt; }
            if (v.w > tht) { v.w -= ht; acc.w += dt; }
        }
        y[i] = acc;
    }
}

extern "C" void kernel_launch(void* const* d_in, const int* in_sizes, int n_in,
                              void* d_out, int out_size) {
    const float* x     = (const float*)d_in[0];  // 16,777,216
    const float* d     = (const float*)d_in[1];  // 2
    const float* h     = (const float*)d_in[2];  // 2
    const float* theta = (const float*)d_in[3];  // 2
    float* y = (float*)d_out;

    int n  = in_sizes[0];
    int n4 = n >> 2;  // n is 16,777,216 -> divisible by 4

    coef_kernel<<<1, 32>>>(d, h, theta);

    const int threads = 256;
    int blocks = 2048;  // 524,288 threads, each handles ~8 float4's
    int need = (n4 + threads - 1) / threads;
    if (need < blocks) blocks = need;

    fsneuron_kernel<<<blocks, threads>>>((const float4*)x, (float4*)y, n4);
}

// round 2
// speedup vs baseline: 1.2793x; 1.2793x over previous
#include <cuda_runtime.h>

// FSNeuronDecoupled: T=8 spiking-threshold scan over x[8,2097152,1] fp32.
// Per element e: v=x[e]; for t=0..7: s=(v>th_t); v-=h_t*s; y+=d_t*s
// th_t = theta[g]^-(t+1), h_t = h[g]^-(t+1), d_t = d[g]^-(t+1), g = t<4?0:1.
//
// Single fused kernel. Coefficients are running reciprocal-power products
// per thread (no pre-kernel). 4 float4 loads front-batched per thread for
// MLP; streaming cache hints since data is touched exactly once.

#define THREADS 256
#define UNROLL  4

__device__ __forceinline__ float4 ldcs4(const float4* p) {
    return __ldcs(p);
}

__global__ __launch_bounds__(THREADS)
void fsneuron_kernel(const float4* __restrict__ x,
                     float4* __restrict__ y,
                     const float* __restrict__ dp_,
                     const float* __restrict__ hp_,
                     const float* __restrict__ thp_,
                     int n4) {
    // Broadcast scalar loads + correctly-rounded reciprocals (exact for 2.0).
    const float rth0 = __frcp_rn(__ldg(&thp_[0]));
    const float rth1 = __frcp_rn(__ldg(&thp_[1]));
    const float rh0  = __frcp_rn(__ldg(&hp_[0]));
    const float rh1  = __frcp_rn(__ldg(&hp_[1]));
    const float rd0  = __frcp_rn(__ldg(&dp_[0]));
    const float rd1  = __frcp_rn(__ldg(&dp_[1]));

    const int base = blockIdx.x * (THREADS * UNROLL) + threadIdx.x;

    float4 v[UNROLL];
    float4 a[UNROLL];
    bool full = (base + (UNROLL - 1) * THREADS) < n4;

    if (full) {
#pragma unroll
        for (int k = 0; k < UNROLL; k++)
            v[k] = ldcs4(&x[base + k * THREADS]);
    } else {
#pragma unroll
        for (int k = 0; k < UNROLL; k++) {
            int i = base + k * THREADS;
            v[k] = (i < n4) ? ldcs4(&x[i]) : make_float4(0.f, 0.f, 0.f, 0.f);
        }
    }
#pragma unroll
    for (int k = 0; k < UNROLL; k++)
        a[k] = make_float4(0.f, 0.f, 0.f, 0.f);

#define LANE(vv, aa) { if (vv > thp) { vv -= hp; aa += dpw; } }
#define STEP()                                    \
    {                                             \
        _Pragma("unroll")                         \
        for (int k = 0; k < UNROLL; k++) {        \
            LANE(v[k].x, a[k].x);                 \
            LANE(v[k].y, a[k].y);                 \
            LANE(v[k].z, a[k].z);                 \
            LANE(v[k].w, a[k].w);                 \
        }                                         \
    }

    // Grain 0: t = 0..3, coefficient = r^(t+1)
    float thp = rth0, hp = rh0, dpw = rd0;
#pragma unroll
    for (int t = 0; t < 4; t++) {
        STEP();
        thp *= rth0; hp *= rh0; dpw *= rd0;
    }

    // Grain 1: t = 4..7, coefficient = r1^(t+1), starting at power 5.
    {
        float r2 = rth1 * rth1; thp = r2 * r2 * rth1;
        float s2 = rh1  * rh1;  hp  = s2 * s2 * rh1;
        float u2 = rd1  * rd1;  dpw = u2 * u2 * rd1;
    }
#pragma unroll
    for (int t = 4; t < 8; t++) {
        STEP();
        thp *= rth1; hp *= rh1; dpw *= rd1;
    }

#undef STEP
#undef LANE

    if (full) {
#pragma unroll
        for (int k = 0; k < UNROLL; k++)
            __stcs(&y[base + k * THREADS], a[k]);
    } else {
#pragma unroll
        for (int k = 0; k < UNROLL; k++) {
            int i = base + k * THREADS;
            if (i < n4) __stcs(&y[i], a[k]);
        }
    }
}

extern "C" void kernel_launch(void* const* d_in, const int* in_sizes, int n_in,
                              void* d_out, int out_size) {
    const float* x     = (const float*)d_in[0];  // 16,777,216 fp32
    const float* d     = (const float*)d_in[1];  // 2
    const float* h     = (const float*)d_in[2];  // 2
    const float* theta = (const float*)d_in[3];  // 2
    float* y = (float*)d_out;

    int n  = in_sizes[0];
    int n4 = n >> 2;                       // 4,194,304 float4
    int per_block = THREADS * UNROLL;      // 1024 float4 per block
    int blocks = (n4 + per_block - 1) / per_block;  // 4096

    fsneuron_kernel<<<blocks, THREADS>>>((const float4*)x, (float4*)y,
                                         d, h, theta, n4);
}